// round 10
// baseline (speedup 1.0000x reference)
#include <cuda_runtime.h>
#include <cuda_fp16.h>
#include <cstdint>

#define B_TOTAL  4096
#define T_TOT    64
#define KDIM     192
#define DT       0.01f

#define CTA_ROWS 32
#define NTH      256          // 8 warps; phase1: n24/warp, phase2: 2 complex n8 + 1 real n8
#define NGRID    (B_TOTAL / CTA_ROWS)   // 128

__device__ __half g_W1h[192 * 192];   // rows 0-127 = cW1, 128-191 = rW1  ([n][k])
__device__ __half g_W2ch[128 * 128];
__device__ __half g_W2rh[64 * 64];
__device__ float  g_b1[192];
__device__ float  g_b2c[128];
__device__ float  g_b2r[64];

__global__ void pack_weights(const float* __restrict__ cW1, const float* __restrict__ cb1,
                             const float* __restrict__ cW2, const float* __restrict__ cb2,
                             const float* __restrict__ rW1, const float* __restrict__ rb1,
                             const float* __restrict__ rW2, const float* __restrict__ rb2)
{
    int i = blockIdx.x * blockDim.x + threadIdx.x;
    if (i < 192 * 192) {
        int n = i / 192, k = i % 192;
        float v = (n < 128) ? cW1[n * 192 + k] : rW1[(n - 128) * 192 + k];
        g_W1h[i] = __float2half_rn(v);
    }
    if (i < 128 * 128) g_W2ch[i] = __float2half_rn(cW2[i]);
    if (i < 64 * 64)   g_W2rh[i] = __float2half_rn(rW2[i]);
    if (i < 192) g_b1[i]  = (i < 128) ? cb1[i] : rb1[i - 128];
    if (i < 128) g_b2c[i] = cb2[i];
    if (i < 64)  g_b2r[i] = rb2[i];
}

__device__ __forceinline__ uint32_t smem_to_u32(const void* p) {
    uint32_t a;
    asm("{ .reg .u64 t; cvta.to.shared.u64 t, %1; cvt.u32.u64 %0, t; }" : "=r"(a) : "l"(p));
    return a;
}

#define LDSM4(a, addr) \
    asm volatile("ldmatrix.sync.aligned.m8n8.x4.shared.b16 {%0,%1,%2,%3}, [%4];" \
                 : "=r"((a)[0]), "=r"((a)[1]), "=r"((a)[2]), "=r"((a)[3]) : "r"(addr))

#define MMA16816(d, a, b) \
    asm volatile("mma.sync.aligned.m16n8k16.row.col.f32.f16.f16.f32 " \
                 "{%0,%1,%2,%3}, {%4,%5,%6,%7}, {%8,%9}, {%0,%1,%2,%3};" \
                 : "+f"((d)[0]), "+f"((d)[1]), "+f"((d)[2]), "+f"((d)[3]) \
                 : "r"((a)[0]), "r"((a)[1]), "r"((a)[2]), "r"((a)[3]), \
                   "r"((b)[0]), "r"((b)[1]))

#define STCG_F2(p, v) \
    asm volatile("st.global.cg.v2.f32 [%0], {%1, %2};" :: "l"(p), "f"((v).x), "f"((v).y) : "memory")

__device__ __forceinline__ float exp_t(float x) {
    return 1.f + x * (1.f + x * (0.5f + x * (0.16666667f + x * 0.041666668f)));
}
__device__ __forceinline__ float sin_t(float x) { float x2 = x * x; return x * (1.f + x2 * (-0.16666667f + x2 * 0.0083333333f)); }
__device__ __forceinline__ float cos_t(float x) { float x2 = x * x; return 1.f + x2 * (-0.5f + x2 * 0.041666668f); }

#define H_STRIDE  200
#define OFF_HH    12800
#define SMEM_TOTAL 25600

__global__ __launch_bounds__(NTH, 1)
void koopman_mma(const float* __restrict__ x, float* __restrict__ out)
{
    extern __shared__ char smem[];
    __half* y_h = (__half*)smem;
    __half* h_h = (__half*)(smem + OFF_HH);

    const int tid  = threadIdx.x;
    const int lane = tid & 31;
    const int wrp  = tid >> 5;          // 0..7
    const int gid  = lane >> 2;
    const int tig  = lane & 3;
    const int b0   = blockIdx.x * CTA_ROWS;

    // ---- B fragments, loaded once ----
    // Phase1: warp owns n8-tiles {3w, 3w+1, 3w+2} of the 192-col GEMM1
    uint32_t b1f[12][3][2];
    #pragma unroll
    for (int kk = 0; kk < 12; kk++)
        #pragma unroll
        for (int j = 0; j < 3; j++) {
            int n = 24 * wrp + 8 * j + gid;
            b1f[kk][j][0] = *(const uint32_t*)&g_W1h[n * 192 + 16 * kk + 2 * tig];
            b1f[kk][j][1] = *(const uint32_t*)&g_W1h[n * 192 + 16 * kk + 8 + 2 * tig];
        }
    // Phase2: warp owns complex n8-tiles {2w, 2w+1} and real n8-tile {w}
    uint32_t b2c[2][8][2];
    #pragma unroll
    for (int j = 0; j < 2; j++)
        #pragma unroll
        for (int kk = 0; kk < 8; kk++) {
            int n = 16 * wrp + 8 * j + gid;
            b2c[j][kk][0] = *(const uint32_t*)&g_W2ch[n * 128 + 16 * kk + 2 * tig];
            b2c[j][kk][1] = *(const uint32_t*)&g_W2ch[n * 128 + 16 * kk + 8 + 2 * tig];
        }
    uint32_t b2r[4][2];
    #pragma unroll
    for (int kk = 0; kk < 4; kk++) {
        int n = 8 * wrp + gid;
        b2r[kk][0] = *(const uint32_t*)&g_W2rh[n * 64 + 16 * kk + 2 * tig];
        b2r[kk][1] = *(const uint32_t*)&g_W2rh[n * 64 + 16 * kk + 8 + 2 * tig];
    }

    // ---- biases ----
    float2 b1b[3], b2cb[2], b2rb;
    #pragma unroll
    for (int j = 0; j < 3; j++) {
        int c = 24 * wrp + 8 * j + 2 * tig;
        b1b[j] = make_float2(g_b1[c], g_b1[c + 1]);
    }
    #pragma unroll
    for (int j = 0; j < 2; j++) {
        int c = 16 * wrp + 8 * j + 2 * tig;
        b2cb[j] = make_float2(g_b2c[c], g_b2c[c + 1]);
    }
    { int c = 8 * wrp + 2 * tig; b2rb = make_float2(g_b2r[c], g_b2r[c + 1]); }

    // ---- fp32 state in registers, matching phase-2 D-fragment coords ----
    // complex: yC[j][mt][rr] at (row = mt*16+rr*8+gid, col = 16w+8j+2tig)
    // real:    yR[mt][rr]    at (row, col = 128+8w+2tig)
    float2 yC[2][2][2], yR[2][2];
    #pragma unroll
    for (int j = 0; j < 2; j++)
        #pragma unroll
        for (int mt = 0; mt < 2; mt++)
            #pragma unroll
            for (int rr = 0; rr < 2; rr++) {
                int row = mt * 16 + rr * 8 + gid;
                int col = 16 * wrp + 8 * j + 2 * tig;
                float2 v = *(const float2*)&x[(size_t)(b0 + row) * T_TOT * KDIM + col];
                yC[j][mt][rr] = v;
                *(__half2*)&y_h[row * H_STRIDE + col] = __floats2half2_rn(v.x, v.y);
            }
    #pragma unroll
    for (int mt = 0; mt < 2; mt++)
        #pragma unroll
        for (int rr = 0; rr < 2; rr++) {
            int row = mt * 16 + rr * 8 + gid;
            int col = 128 + 8 * wrp + 2 * tig;
            float2 v = *(const float2*)&x[(size_t)(b0 + row) * T_TOT * KDIM + col];
            yR[mt][rr] = v;
            *(__half2*)&y_h[row * H_STRIDE + col] = __floats2half2_rn(v.x, v.y);
        }

    float* outpC = out + (size_t)(b0 + gid) * T_TOT * KDIM + 16 * wrp + 2 * tig;
    float* outpR = out + (size_t)(b0 + gid) * T_TOT * KDIM + 128 + 8 * wrp + 2 * tig;

    const uint32_t rowoff = ((((lane >> 3) & 1) * 8 + (lane & 7))) * (H_STRIDE * 2)
                          + (lane >> 4) * 16;
    const uint32_t yh_u = smem_to_u32(y_h) + rowoff;
    const uint32_t hh_u = smem_to_u32(h_h) + rowoff;

    __syncthreads();

    for (int t = 0; t < T_TOT; t++) {
        // ---------- phase 1: h1 = relu(y @ W1^T + b1), K=192, 3 n8-tiles ----------
        float d1[2][3][4];
        #pragma unroll
        for (int mt = 0; mt < 2; mt++)
            #pragma unroll
            for (int j = 0; j < 3; j++)
                #pragma unroll
                for (int e = 0; e < 4; e++) d1[mt][j][e] = 0.f;

        #pragma unroll
        for (int kk = 0; kk < 12; kk++) {
            uint32_t a0[4], a1[4];
            LDSM4(a0, yh_u + kk * 32);
            LDSM4(a1, yh_u + (16 * H_STRIDE * 2) + kk * 32);
            #pragma unroll
            for (int j = 0; j < 3; j++) {
                MMA16816(d1[0][j], a0, b1f[kk][j]);
                MMA16816(d1[1][j], a1, b1f[kk][j]);
            }
        }
        // epilogue 1
        #pragma unroll
        for (int mt = 0; mt < 2; mt++)
            #pragma unroll
            for (int j = 0; j < 3; j++) {
                int col = 24 * wrp + 8 * j + 2 * tig;
                int row = mt * 16 + gid;
                float h0 = fmaxf(d1[mt][j][0] + b1b[j].x, 0.f);
                float h1 = fmaxf(d1[mt][j][1] + b1b[j].y, 0.f);
                *(__half2*)&h_h[row * H_STRIDE + col] = __floats2half2_rn(h0, h1);
                h0 = fmaxf(d1[mt][j][2] + b1b[j].x, 0.f);
                h1 = fmaxf(d1[mt][j][3] + b1b[j].y, 0.f);
                *(__half2*)&h_h[(row + 8) * H_STRIDE + col] = __floats2half2_rn(h0, h1);
            }
        __syncthreads();

        // ---------- phase 2: complex K=128 (2 tiles) + real K=64 (1 tile) ----------
        float d2c[2][2][4], d2r[2][4];
        #pragma unroll
        for (int mt = 0; mt < 2; mt++) {
            #pragma unroll
            for (int j = 0; j < 2; j++)
                #pragma unroll
                for (int e = 0; e < 4; e++) d2c[mt][j][e] = 0.f;
            #pragma unroll
            for (int e = 0; e < 4; e++) d2r[mt][e] = 0.f;
        }
        #pragma unroll
        for (int kk = 0; kk < 8; kk++) {
            uint32_t a0[4], a1[4];
            LDSM4(a0, hh_u + kk * 32);
            LDSM4(a1, hh_u + (16 * H_STRIDE * 2) + kk * 32);
            #pragma unroll
            for (int j = 0; j < 2; j++) {
                MMA16816(d2c[0][j], a0, b2c[j][kk]);
                MMA16816(d2c[1][j], a1, b2c[j][kk]);
            }
        }
        #pragma unroll
        for (int kk = 0; kk < 4; kk++) {
            uint32_t a0[4], a1[4];
            LDSM4(a0, hh_u + 256 + kk * 32);
            LDSM4(a1, hh_u + (16 * H_STRIDE * 2) + 256 + kk * 32);
            MMA16816(d2r[0], a0, b2r[kk]);
            MMA16816(d2r[1], a1, b2r[kk]);
        }

        // ---------- phase 3: Koopman update + stores ----------
        #pragma unroll
        for (int j = 0; j < 2; j++)
            #pragma unroll
            for (int mt = 0; mt < 2; mt++)
                #pragma unroll
                for (int rr = 0; rr < 2; rr++) {
                    int col = 16 * wrp + 8 * j + 2 * tig;
                    int row = mt * 16 + rr * 8 + gid;
                    float mu = d2c[mt][j][2 * rr]     + b2cb[j].x;
                    float om = d2c[mt][j][2 * rr + 1] + b2cb[j].y;
                    float e = exp_t(DT * mu);
                    float c = cos_t(DT * om);
                    float s = sin_t(DT * om);
                    float2 yp = yC[j][mt][rr];
                    float o0 = e * (c * yp.x - s * yp.y);
                    float o1 = e * (s * yp.x + c * yp.y);
                    yC[j][mt][rr] = make_float2(o0, o1);
                    *(__half2*)&y_h[row * H_STRIDE + col] = __floats2half2_rn(o0, o1);
                    float2 ov = make_float2(o0, o1);
                    STCG_F2(outpC + (size_t)(mt * 16 + rr * 8) * T_TOT * KDIM + 8 * j, ov);
                }
        #pragma unroll
        for (int mt = 0; mt < 2; mt++)
            #pragma unroll
            for (int rr = 0; rr < 2; rr++) {
                int col = 128 + 8 * wrp + 2 * tig;
                int row = mt * 16 + rr * 8 + gid;
                float r0 = d2r[mt][2 * rr]     + b2rb.x;
                float r1 = d2r[mt][2 * rr + 1] + b2rb.y;
                float2 yp = yR[mt][rr];
                float o0 = yp.x * exp_t(DT * r0);
                float o1 = yp.y * exp_t(DT * r1);
                yR[mt][rr] = make_float2(o0, o1);
                *(__half2*)&y_h[row * H_STRIDE + col] = __floats2half2_rn(o0, o1);
                float2 ov = make_float2(o0, o1);
                STCG_F2(outpR + (size_t)(mt * 16 + rr * 8) * T_TOT * KDIM, ov);
            }
        outpC += KDIM;
        outpR += KDIM;
        __syncthreads();
    }
}

extern "C" void kernel_launch(void* const* d_in, const int* in_sizes, int n_in,
                              void* d_out, int out_size)
{
    const float* x   = (const float*)d_in[0];
    const float* cW1 = (const float*)d_in[1];
    const float* cb1 = (const float*)d_in[2];
    const float* cW2 = (const float*)d_in[3];
    const float* cb2 = (const float*)d_in[4];
    const float* rW1 = (const float*)d_in[5];
    const float* rb1 = (const float*)d_in[6];
    const float* rW2 = (const float*)d_in[7];
    const float* rb2 = (const float*)d_in[8];
    float* out = (float*)d_out;

    pack_weights<<<(192 * 192 + 255) / 256, 256>>>(cW1, cb1, cW2, cb2, rW1, rb1, rW2, rb2);

    cudaFuncSetAttribute(koopman_mma, cudaFuncAttributeMaxDynamicSharedMemorySize, SMEM_TOTAL);
    koopman_mma<<<NGRID, NTH, SMEM_TOTAL>>>(x, out);
}

// round 11
// speedup vs baseline: 1.2175x; 1.2175x over previous
#include <cuda_runtime.h>
#include <cuda_fp16.h>
#include <cstdint>

#define B_TOTAL  4096
#define T_TOT    64
#define KDIM     192
#define DT       0.01f

#define CTA_ROWS 32
#define NTH      384          // 12 warps = 12 col-tiles of 16
#define NGRID    (B_TOTAL / CTA_ROWS)   // 128

__device__ __half g_W1h[192 * 192];   // rows 0-127 = cW1, 128-191 = rW1  ([n][k])
__device__ __half g_W2ch[128 * 128];
__device__ __half g_W2rh[64 * 64];
__device__ float  g_b1[192];
__device__ float  g_b2c[128];
__device__ float  g_b2r[64];

__global__ void pack_weights(const float* __restrict__ cW1, const float* __restrict__ cb1,
                             const float* __restrict__ cW2, const float* __restrict__ cb2,
                             const float* __restrict__ rW1, const float* __restrict__ rb1,
                             const float* __restrict__ rW2, const float* __restrict__ rb2)
{
    int i = blockIdx.x * blockDim.x + threadIdx.x;
    if (i < 192 * 192) {
        int n = i / 192, k = i % 192;
        float v = (n < 128) ? cW1[n * 192 + k] : rW1[(n - 128) * 192 + k];
        g_W1h[i] = __float2half_rn(v);
    }
    if (i < 128 * 128) g_W2ch[i] = __float2half_rn(cW2[i]);
    if (i < 64 * 64)   g_W2rh[i] = __float2half_rn(rW2[i]);
    if (i < 192) g_b1[i]  = (i < 128) ? cb1[i] : rb1[i - 128];
    if (i < 128) g_b2c[i] = cb2[i];
    if (i < 64)  g_b2r[i] = rb2[i];
}

__device__ __forceinline__ uint32_t smem_to_u32(const void* p) {
    uint32_t a;
    asm("{ .reg .u64 t; cvta.to.shared.u64 t, %1; cvt.u32.u64 %0, t; }" : "=r"(a) : "l"(p));
    return a;
}

#define LDSM4(a, addr) \
    asm volatile("ldmatrix.sync.aligned.m8n8.x4.shared.b16 {%0,%1,%2,%3}, [%4];" \
                 : "=r"((a)[0]), "=r"((a)[1]), "=r"((a)[2]), "=r"((a)[3]) : "r"(addr))

#define MMA16816(d, a, b) \
    asm volatile("mma.sync.aligned.m16n8k16.row.col.f32.f16.f16.f32 " \
                 "{%0,%1,%2,%3}, {%4,%5,%6,%7}, {%8,%9}, {%0,%1,%2,%3};" \
                 : "+f"((d)[0]), "+f"((d)[1]), "+f"((d)[2]), "+f"((d)[3]) \
                 : "r"((a)[0]), "r"((a)[1]), "r"((a)[2]), "r"((a)[3]), \
                   "r"((b)[0]), "r"((b)[1]))

#define STCG_F2(p, v) \
    asm volatile("st.global.cg.v2.f32 [%0], {%1, %2};" :: "l"(p), "f"((v).x), "f"((v).y) : "memory")

__device__ __forceinline__ float exp_t(float x) {
    return 1.f + x * (1.f + x * (0.5f + x * (0.16666667f + x * 0.041666668f)));
}
__device__ __forceinline__ float sin_t(float x) { float x2 = x * x; return x * (1.f + x2 * (-0.16666667f + x2 * 0.0083333333f)); }
__device__ __forceinline__ float cos_t(float x) { float x2 = x * x; return 1.f + x2 * (-0.5f + x2 * 0.041666668f); }

__device__ __forceinline__ uint32_t h2u(float a, float b) {
    __half2 h = __floats2half2_rn(a, b);
    return *reinterpret_cast<uint32_t*>(&h);
}

#define H_STRIDE  200
#define OFF_HH    12800
#define SMEM_TOTAL 25600

__global__ __launch_bounds__(NTH, 1)
void koopman_mma(const float* __restrict__ x, float* __restrict__ out)
{
    extern __shared__ char smem[];
    __half* y_h = (__half*)smem;
    __half* h_h = (__half*)(smem + OFF_HH);

    const int tid  = threadIdx.x;
    const int lane = tid & 31;
    const int wrp  = tid >> 5;          // 0..11, output col-tile n0 = 16*wrp
    const int gid  = lane >> 2;
    const int tig  = lane & 3;
    const int n0   = wrp * 16;
    const bool is_real = (wrp >= 8);
    const int rw   = wrp - 8;           // real-head chunk index (valid when is_real)
    const int b0   = blockIdx.x * CTA_ROWS;

    // ---- register-resident B fragments, slot-permuted: slot 0 = OWN k-chunk ----
    uint32_t b1f[12][4];
    #pragma unroll
    for (int h = 0; h < 2; h++) {
        int n = n0 + 8 * h + gid;
        b1f[0][2*h]   = *(const uint32_t*)&g_W1h[n * 192 + 16 * wrp + 2 * tig];
        b1f[0][2*h+1] = *(const uint32_t*)&g_W1h[n * 192 + 16 * wrp + 8 + 2 * tig];
    }
    #pragma unroll
    for (int i = 0; i < 11; i++) {
        int kk = i + (i >= wrp);
        #pragma unroll
        for (int h = 0; h < 2; h++) {
            int n = n0 + 8 * h + gid;
            b1f[i+1][2*h]   = *(const uint32_t*)&g_W1h[n * 192 + 16 * kk + 2 * tig];
            b1f[i+1][2*h+1] = *(const uint32_t*)&g_W1h[n * 192 + 16 * kk + 8 + 2 * tig];
        }
    }
    uint32_t b2f[8][4];
    if (!is_real) {
        #pragma unroll
        for (int h = 0; h < 2; h++) {
            int n = n0 + 8 * h + gid;
            b2f[0][2*h]   = *(const uint32_t*)&g_W2ch[n * 128 + 16 * wrp + 2 * tig];
            b2f[0][2*h+1] = *(const uint32_t*)&g_W2ch[n * 128 + 16 * wrp + 8 + 2 * tig];
        }
        #pragma unroll
        for (int i = 0; i < 7; i++) {
            int kk = i + (i >= wrp);
            #pragma unroll
            for (int h = 0; h < 2; h++) {
                int n = n0 + 8 * h + gid;
                b2f[i+1][2*h]   = *(const uint32_t*)&g_W2ch[n * 128 + 16 * kk + 2 * tig];
                b2f[i+1][2*h+1] = *(const uint32_t*)&g_W2ch[n * 128 + 16 * kk + 8 + 2 * tig];
            }
        }
    } else {
        #pragma unroll
        for (int h = 0; h < 2; h++) {
            int n = n0 - 128 + 8 * h + gid;
            b2f[0][2*h]   = *(const uint32_t*)&g_W2rh[n * 64 + 16 * rw + 2 * tig];
            b2f[0][2*h+1] = *(const uint32_t*)&g_W2rh[n * 64 + 16 * rw + 8 + 2 * tig];
        }
        #pragma unroll
        for (int i = 0; i < 3; i++) {
            int kk = i + (i >= rw);
            #pragma unroll
            for (int h = 0; h < 2; h++) {
                int n = n0 - 128 + 8 * h + gid;
                b2f[i+1][2*h]   = *(const uint32_t*)&g_W2rh[n * 64 + 16 * kk + 2 * tig];
                b2f[i+1][2*h+1] = *(const uint32_t*)&g_W2rh[n * 64 + 16 * kk + 8 + 2 * tig];
            }
        }
    }

    // ---- biases ----
    float2 b1b[2], b2b[2];
    #pragma unroll
    for (int nt = 0; nt < 2; nt++) {
        int col = n0 + 8 * nt + 2 * tig;
        b1b[nt] = make_float2(g_b1[col], g_b1[col + 1]);
        b2b[nt] = is_real ? make_float2(g_b2r[col - 128], g_b2r[col - 127])
                          : make_float2(g_b2c[col],       g_b2c[col + 1]);
    }

    // ---- fp32 state in registers (D-frag coords = A-frag coords of own chunk) ----
    float2 yreg[2][2][2];   // [mt][nt][rr]: row = mt*16+rr*8+gid, col = n0+nt*8+2tig
    #pragma unroll
    for (int mt = 0; mt < 2; mt++)
        #pragma unroll
        for (int nt = 0; nt < 2; nt++)
            #pragma unroll
            for (int rr = 0; rr < 2; rr++) {
                int row = mt * 16 + rr * 8 + gid;
                int col = n0 + nt * 8 + 2 * tig;
                float2 v = *(const float2*)&x[(size_t)(b0 + row) * T_TOT * KDIM + col];
                yreg[mt][nt][rr] = v;
                *(__half2*)&y_h[row * H_STRIDE + col] = __floats2half2_rn(v.x, v.y);
            }

    float* outp = out + (size_t)(b0 + gid) * T_TOT * KDIM + n0 + 2 * tig;

    const uint32_t rowoff = ((((lane >> 3) & 1) * 8 + (lane & 7))) * (H_STRIDE * 2)
                          + (lane >> 4) * 16;
    const uint32_t yh_u = smem_to_u32(y_h) + rowoff;
    const uint32_t hh_u = smem_to_u32(h_h) + rowoff;

    for (int t = 0; t < T_TOT; t++) {
        // ---------- phase 1 own-chunk MMA (registers only) — runs BEFORE the barrier ----------
        float d1[2][2][4];
        #pragma unroll
        for (int mt = 0; mt < 2; mt++)
            #pragma unroll
            for (int nt = 0; nt < 2; nt++)
                #pragma unroll
                for (int e = 0; e < 4; e++) d1[mt][nt][e] = 0.f;
        {
            uint32_t aw0[4] = { h2u(yreg[0][0][0].x, yreg[0][0][0].y), h2u(yreg[0][0][1].x, yreg[0][0][1].y),
                                h2u(yreg[0][1][0].x, yreg[0][1][0].y), h2u(yreg[0][1][1].x, yreg[0][1][1].y) };
            uint32_t aw1[4] = { h2u(yreg[1][0][0].x, yreg[1][0][0].y), h2u(yreg[1][0][1].x, yreg[1][0][1].y),
                                h2u(yreg[1][1][0].x, yreg[1][1][0].y), h2u(yreg[1][1][1].x, yreg[1][1][1].y) };
            MMA16816(d1[0][0], aw0, &b1f[0][0]);
            MMA16816(d1[0][1], aw0, &b1f[0][2]);
            MMA16816(d1[1][0], aw1, &b1f[0][0]);
            MMA16816(d1[1][1], aw1, &b1f[0][2]);
        }
        __syncthreads();   // y_h (this step) visible CTA-wide

        // ---------- phase 1 remaining 11 chunks ----------
        #pragma unroll
        for (int i = 0; i < 11; i++) {
            int kk = i + (i >= wrp);
            uint32_t a0[4], a1[4];
            LDSM4(a0, yh_u + kk * 32);
            LDSM4(a1, yh_u + (16 * H_STRIDE * 2) + kk * 32);
            MMA16816(d1[0][0], a0, &b1f[i+1][0]);
            MMA16816(d1[0][1], a0, &b1f[i+1][2]);
            MMA16816(d1[1][0], a1, &b1f[i+1][0]);
            MMA16816(d1[1][1], a1, &b1f[i+1][2]);
        }

        // ---------- epilogue 1: bias+relu -> hf2 regs (A-frag of own h-chunk) + h_h ----------
        uint32_t hf2[2][4];
        #pragma unroll
        for (int mt = 0; mt < 2; mt++)
            #pragma unroll
            for (int nt = 0; nt < 2; nt++) {
                int col = n0 + 8 * nt + 2 * tig;
                int row = mt * 16 + gid;
                uint32_t ha = h2u(fmaxf(d1[mt][nt][0] + b1b[nt].x, 0.f),
                                  fmaxf(d1[mt][nt][1] + b1b[nt].y, 0.f));
                uint32_t hb = h2u(fmaxf(d1[mt][nt][2] + b1b[nt].x, 0.f),
                                  fmaxf(d1[mt][nt][3] + b1b[nt].y, 0.f));
                hf2[mt][nt * 2]     = ha;
                hf2[mt][nt * 2 + 1] = hb;
                *(uint32_t*)&h_h[row * H_STRIDE + col]       = ha;
                *(uint32_t*)&h_h[(row + 8) * H_STRIDE + col] = hb;
            }

        // ---------- phase 2 own-chunk MMA (registers only) — BEFORE the barrier ----------
        float d2[2][2][4];
        #pragma unroll
        for (int mt = 0; mt < 2; mt++)
            #pragma unroll
            for (int nt = 0; nt < 2; nt++)
                #pragma unroll
                for (int e = 0; e < 4; e++) d2[mt][nt][e] = 0.f;
        MMA16816(d2[0][0], hf2[0], &b2f[0][0]);
        MMA16816(d2[0][1], hf2[0], &b2f[0][2]);
        MMA16816(d2[1][0], hf2[1], &b2f[0][0]);
        MMA16816(d2[1][1], hf2[1], &b2f[0][2]);
        __syncthreads();   // h_h visible CTA-wide (full barrier: no cross-group race)

        // ---------- phase 2 remaining chunks ----------
        if (!is_real) {
            #pragma unroll
            for (int i = 0; i < 7; i++) {
                int kk = i + (i >= wrp);
                uint32_t a0[4], a1[4];
                LDSM4(a0, hh_u + kk * 32);
                LDSM4(a1, hh_u + (16 * H_STRIDE * 2) + kk * 32);
                MMA16816(d2[0][0], a0, &b2f[i+1][0]);
                MMA16816(d2[0][1], a0, &b2f[i+1][2]);
                MMA16816(d2[1][0], a1, &b2f[i+1][0]);
                MMA16816(d2[1][1], a1, &b2f[i+1][2]);
            }
        } else {
            #pragma unroll
            for (int i = 0; i < 3; i++) {
                int kk = i + (i >= rw);
                uint32_t a0[4], a1[4];
                LDSM4(a0, hh_u + 256 + kk * 32);
                LDSM4(a1, hh_u + (16 * H_STRIDE * 2) + 256 + kk * 32);
                MMA16816(d2[0][0], a0, &b2f[i+1][0]);
                MMA16816(d2[0][1], a0, &b2f[i+1][2]);
                MMA16816(d2[1][0], a1, &b2f[i+1][0]);
                MMA16816(d2[1][1], a1, &b2f[i+1][2]);
            }
        }

        // ---------- phase 3: Koopman update + stores ----------
        #pragma unroll
        for (int mt = 0; mt < 2; mt++)
            #pragma unroll
            for (int nt = 0; nt < 2; nt++) {
                int col = n0 + 8 * nt + 2 * tig;
                #pragma unroll
                for (int rr = 0; rr < 2; rr++) {
                    int row = mt * 16 + rr * 8 + gid;
                    float v0 = d2[mt][nt][2 * rr]     + b2b[nt].x;
                    float v1 = d2[mt][nt][2 * rr + 1] + b2b[nt].y;
                    float2 yp = yreg[mt][nt][rr];
                    float o0, o1;
                    if (!is_real) {
                        float e = exp_t(DT * v0);
                        float c = cos_t(DT * v1);
                        float s = sin_t(DT * v1);
                        o0 = e * (c * yp.x - s * yp.y);
                        o1 = e * (s * yp.x + c * yp.y);
                    } else {
                        o0 = yp.x * exp_t(DT * v0);
                        o1 = yp.y * exp_t(DT * v1);
                    }
                    yreg[mt][nt][rr] = make_float2(o0, o1);
                    *(__half2*)&y_h[row * H_STRIDE + col] = __floats2half2_rn(o0, o1);
                    float2 ov = make_float2(o0, o1);
                    STCG_F2(outp + (size_t)(mt * 16 + rr * 8) * T_TOT * KDIM + nt * 8, ov);
                }
            }
        outp += KDIM;
        // no trailing barrier: next iteration's top barrier orders y_h writes vs reads
    }
}

extern "C" void kernel_launch(void* const* d_in, const int* in_sizes, int n_in,
                              void* d_out, int out_size)
{
    const float* x   = (const float*)d_in[0];
    const float* cW1 = (const float*)d_in[1];
    const float* cb1 = (const float*)d_in[2];
    const float* cW2 = (const float*)d_in[3];
    const float* cb2 = (const float*)d_in[4];
    const float* rW1 = (const float*)d_in[5];
    const float* rb1 = (const float*)d_in[6];
    const float* rW2 = (const float*)d_in[7];
    const float* rb2 = (const float*)d_in[8];
    float* out = (float*)d_out;

    pack_weights<<<(192 * 192 + 255) / 256, 256>>>(cW1, cb1, cW2, cb2, rW1, rb1, rW2, rb2);

    cudaFuncSetAttribute(koopman_mma, cudaFuncAttributeMaxDynamicSharedMemorySize, SMEM_TOTAL);
    koopman_mma<<<NGRID, NTH, SMEM_TOTAL>>>(x, out);
}